// round 5
// baseline (speedup 1.0000x reference)
#include <cuda_runtime.h>

typedef unsigned long long u64;

#define H       128
#define SEQ     1024
#define MBLK    4
#define NCTAS   128
#define NTHR    512
#define COUT    10

#define NG      16          // 4-k groups per kh half (64 k's per thread)
#define RG      9           // register-resident weight groups
#define SG      (NG - RG)   // 7 groups from smem

// ---- dynamic smem layout (bytes, 16B aligned) ----
#define WS_OFF    0
#define WS_BYTES  (SG * 4 * 256 * 16)       // 114688: ulonglong2 [(sg*4+q)][slice]
#define PB_OFF    (WS_OFF + WS_BYTES)
#define PB_BYTES  (2 * 256 * 16)            // 8192: float4 per (team, cell)
#define XS_OFF    (PB_OFF + PB_BYTES)
#define XS_BYTES  (MBLK * SEQ * 4)          // 16384
#define WPS_OFF   (XS_OFF + XS_BYTES)
#define WPS_BYTES (H * COUT * 4)            // 5120
#define HS_OFF    (WPS_OFF + WPS_BYTES)
#define HS_BYTES  (MBLK * H * 4)            // 2048
#define SMEM_TOTAL (HS_OFF + HS_BYTES)      // 146432

__device__ __forceinline__ u64 pk2(float lo, float hi) {
    u64 r;
    asm("mov.b64 %0, {%1, %2};" : "=l"(r) : "f"(lo), "f"(hi));
    return r;
}
__device__ __forceinline__ void upk2(u64 v, float& lo, float& hi) {
    asm("mov.b64 {%0, %1}, %2;" : "=f"(lo), "=f"(hi) : "l"(v));
}
__device__ __forceinline__ u64 ffma2(u64 a, u64 b, u64 c) {
    u64 d;
    asm("fma.rn.f32x2 %0, %1, %2, %3;" : "=l"(d) : "l"(a), "l"(b), "l"(c));
    return d;
}

// Overflow-safe fast tanh / sigmoid (validated rel_err ~3e-7 across R1-R4).
__device__ __forceinline__ float tanh_fast(float x) {
    float a = fabsf(x);
    float e = __expf(2.0f * a);
    float r = 1.0f - __fdividef(2.0f, e + 1.0f);
    return copysignf(r, x);
}
__device__ __forceinline__ float sigmoid_fast(float x) {
    float e = __expf(-x);
    return __fdividef(1.0f, 1.0f + e);
}

__global__ void __launch_bounds__(NTHR, 1)
lstm_persistent_kernel(const float* __restrict__ x,
                       const float* __restrict__ Wgx, const float* __restrict__ Wgh, const float* __restrict__ bg,
                       const float* __restrict__ Wix, const float* __restrict__ Wih, const float* __restrict__ bi,
                       const float* __restrict__ Wfx, const float* __restrict__ Wfh, const float* __restrict__ bf,
                       const float* __restrict__ Wox, const float* __restrict__ Woh, const float* __restrict__ bo,
                       const float* __restrict__ Wph, const float* __restrict__ bp,
                       float* __restrict__ out)
{
    extern __shared__ char smem[];
    ulonglong2* ws = (ulonglong2*)(smem + WS_OFF);
    float4*   pbuf = (float4*)(smem + PB_OFF);
    float*     xsm = (float*)(smem + XS_OFF);
    float*     wps = (float*)(smem + WPS_OFF);
    float*      hs = (float*)(smem + HS_OFF);   // [4][128] plain f32

    const int tid = threadIdx.x;
    const int tm  = tid >> 8;           // team 0/1 -> rows {2tm, 2tm+1}
    const int r   = tid & 255;
    const int n   = r & 127;            // column
    const int kh  = r >> 7;             // k-half: [kh*64, kh*64+64)
    const int slice = kh * 128 + n;     // weight slice id (shared across teams)
    const int row0 = tm * 2;            // team's first CTA-local row
    const int m0  = blockIdx.x * MBLK;

    // ---- init smem weights (shared, single copy): groups RG..15 ----
    // ws[(sg*4+q)*256 + slice]: q0={g,i}p0 q1={f,o}p0 q2={g,i}p1 q3={f,o}p1
    for (int i = tid; i < SG * 4 * 256; i += NTHR) {
        int sl  = i & 255;
        int nn  = sl & 127, khh = sl >> 7;
        int rest = i >> 8;
        int sg = rest >> 2, q = rest & 3;
        int p = q >> 1, gp = q & 1;
        int kk = khh * 64 + (RG + sg) * 4 + p * 2;
        const float* WA = gp ? Wfh : Wgh;
        const float* WB = gp ? Woh : Wih;
        ulonglong2 v;
        v.x = pk2(WA[kk*H+nn], WA[(kk+1)*H+nn]);
        v.y = pk2(WB[kk*H+nn], WB[(kk+1)*H+nn]);
        ws[(sg*4+q)*256 + sl] = v;
    }

    // ---- register weights: groups 0..RG-1 ----
    // wreg[g] = {g_p0, i_p0, f_p0, o_p0, g_p1, i_p1, f_p1, o_p1}
    u64 wreg[RG][8];
#pragma unroll
    for (int g = 0; g < RG; g++) {
        int k0 = kh * 64 + g * 4;
        wreg[g][0] = pk2(Wgh[(k0+0)*H+n], Wgh[(k0+1)*H+n]);
        wreg[g][1] = pk2(Wih[(k0+0)*H+n], Wih[(k0+1)*H+n]);
        wreg[g][2] = pk2(Wfh[(k0+0)*H+n], Wfh[(k0+1)*H+n]);
        wreg[g][3] = pk2(Woh[(k0+0)*H+n], Woh[(k0+1)*H+n]);
        wreg[g][4] = pk2(Wgh[(k0+2)*H+n], Wgh[(k0+3)*H+n]);
        wreg[g][5] = pk2(Wih[(k0+2)*H+n], Wih[(k0+3)*H+n]);
        wreg[g][6] = pk2(Wfh[(k0+2)*H+n], Wfh[(k0+3)*H+n]);
        wreg[g][7] = pk2(Woh[(k0+2)*H+n], Woh[(k0+3)*H+n]);
    }

    // ---- gate-phase params: this thread owns cell (row = row0+kh, col n) ----
    const int myrow = row0 + kh;
    const float wxg = Wgx[n], wxi = Wix[n], wxf = Wfx[n], wxo = Wox[n];
    const float bG = bg[(m0+myrow)*H+n], bI = bi[(m0+myrow)*H+n];
    const float bF = bf[(m0+myrow)*H+n], bO = bo[(m0+myrow)*H+n];

    // ---- preload x, Wph, zero h ----
    for (int i = tid; i < MBLK * SEQ; i += NTHR) {
        int mm = i >> 10, tt = i & (SEQ - 1);
        xsm[i] = x[(m0+mm)*SEQ + tt];
    }
    for (int i = tid; i < H * COUT; i += NTHR) wps[i] = Wph[i];
    for (int i = tid; i < MBLK * H; i += NTHR) hs[i] = 0.0f;
    float c = 0.0f;
    __syncthreads();

    // per-thread bases
    const char* wsb = (const char*)ws + (unsigned)slice * 16;
    const float* hrow0 = hs + row0 * 128 + kh * 64;   // h base for m=0 of team
    float4* pw = pbuf + tm * 256 + (1 - kh) * 128 + n; // partner's cell
    const float4* prd = pbuf + tm * 256 + kh * 128 + n; // own cell
    const float* xrow = xsm + myrow * SEQ;
    float* hst = hs + myrow * 128 + n;

    const int barid = tm + 1;

    // ---- time loop: teams fully independent, 2 named barriers per step ----
    for (int t = 0; t < SEQ; t++) {
        u64 aG[2], aI[2], aF[2], aO[2];
#pragma unroll
        for (int m = 0; m < 2; m++) { aG[m]=0ull; aI[m]=0ull; aF[m]=0ull; aO[m]=0ull; }

#pragma unroll
        for (int g = 0; g < NG; g++) {
            u64 wg0, wi0, wf0, wo0, wg1, wi1, wf1, wo1;
            if (g < RG) {
                wg0 = wreg[g][0]; wi0 = wreg[g][1]; wf0 = wreg[g][2]; wo0 = wreg[g][3];
                wg1 = wreg[g][4]; wi1 = wreg[g][5]; wf1 = wreg[g][6]; wo1 = wreg[g][7];
            } else {
                int sg = g - RG;
                ulonglong2 q0 = *(const ulonglong2*)(wsb + ((sg*4+0)*256) * 16);
                ulonglong2 q1 = *(const ulonglong2*)(wsb + ((sg*4+1)*256) * 16);
                ulonglong2 q2 = *(const ulonglong2*)(wsb + ((sg*4+2)*256) * 16);
                ulonglong2 q3 = *(const ulonglong2*)(wsb + ((sg*4+3)*256) * 16);
                wg0 = q0.x; wi0 = q0.y; wf0 = q1.x; wo0 = q1.y;
                wg1 = q2.x; wi1 = q2.y; wf1 = q3.x; wo1 = q3.y;
            }
#pragma unroll
            for (int m = 0; m < 2; m++) {
                ulonglong2 hu = *(const ulonglong2*)(hrow0 + (m << 7) + (g << 2)); // broadcast
                aG[m] = ffma2(hu.x, wg0, aG[m]);
                aI[m] = ffma2(hu.x, wi0, aI[m]);
                aF[m] = ffma2(hu.x, wf0, aF[m]);
                aO[m] = ffma2(hu.x, wo0, aO[m]);
                aG[m] = ffma2(hu.y, wg1, aG[m]);
                aI[m] = ffma2(hu.y, wi1, aI[m]);
                aF[m] = ffma2(hu.y, wf1, aF[m]);
                aO[m] = ffma2(hu.y, wo1, aO[m]);
            }
        }

        // collapse partner's m = 1-kh, ship as one float4
        {
            int pm = 1 - kh;
            float lo, hi, qg, qi, qf, qo;
            upk2(aG[pm], lo, hi); qg = lo + hi;
            upk2(aI[pm], lo, hi); qi = lo + hi;
            upk2(aF[pm], lo, hi); qf = lo + hi;
            upk2(aO[pm], lo, hi); qo = lo + hi;
            *pw = make_float4(qg, qi, qf, qo);
        }
        asm volatile("bar.sync %0, 256;" :: "r"(barid) : "memory");

        // gate phase: own cell (myrow, n)
        {
            float lo, hi, pg, pi, pf, po;
            upk2(aG[kh], lo, hi); pg = lo + hi;
            upk2(aI[kh], lo, hi); pi = lo + hi;
            upk2(aF[kh], lo, hi); pf = lo + hi;
            upk2(aO[kh], lo, hi); po = lo + hi;
            float4 pr = *prd;
            float xv = xrow[t];
            float zg = pg + pr.x + fmaf(xv, wxg, bG);
            float zi = pi + pr.y + fmaf(xv, wxi, bI);
            float zf = pf + pr.z + fmaf(xv, wxf, bF);
            float zo = po + pr.w + fmaf(xv, wxo, bO);
            float gg = tanh_fast(zg);
            float ii = sigmoid_fast(zi);
            float ff = sigmoid_fast(zf);
            float oo = sigmoid_fast(zo);
            c = fmaf(gg, ii, c * ff);
            *hst = tanh_fast(c) * oo;
        }
        asm volatile("bar.sync %0, 256;" :: "r"(barid) : "memory");
    }

    // ---- final projection: out = h @ Wph + bp (needs both teams' h) ----
    __syncthreads();
    if (tid < MBLK * COUT) {
        int m = tid / COUT, cc = tid - m * COUT;
        float ssum = bp[(m0+m)*COUT + cc];
#pragma unroll 16
        for (int k = 0; k < H; k++)
            ssum = fmaf(hs[(m << 7) + k], wps[k*COUT + cc], ssum);
        out[(m0+m)*COUT + cc] = ssum;
    }
}

extern "C" void kernel_launch(void* const* d_in, const int* in_sizes, int n_in,
                              void* d_out, int out_size) {
    const float* x   = (const float*)d_in[0];
    const float* Wgx = (const float*)d_in[1];
    const float* Wgh = (const float*)d_in[2];
    const float* bg  = (const float*)d_in[3];
    const float* Wix = (const float*)d_in[4];
    const float* Wih = (const float*)d_in[5];
    const float* bi  = (const float*)d_in[6];
    const float* Wfx = (const float*)d_in[7];
    const float* Wfh = (const float*)d_in[8];
    const float* bf  = (const float*)d_in[9];
    const float* Wox = (const float*)d_in[10];
    const float* Woh = (const float*)d_in[11];
    const float* bo  = (const float*)d_in[12];
    const float* Wph = (const float*)d_in[13];
    const float* bp  = (const float*)d_in[14];
    float* out = (float*)d_out;

    cudaFuncSetAttribute(lstm_persistent_kernel,
                         cudaFuncAttributeMaxDynamicSharedMemorySize, SMEM_TOTAL);

    lstm_persistent_kernel<<<NCTAS, NTHR, SMEM_TOTAL>>>(
        x, Wgx, Wgh, bg, Wix, Wih, bi, Wfx, Wfh, bf, Wox, Woh, bo, Wph, bp, out);
}

// round 7
// speedup vs baseline: 1.8855x; 1.8855x over previous
#include <cuda_runtime.h>

typedef unsigned long long u64;

#define H       128
#define SEQ     1024
#define MBLK    4
#define NCTAS   128
#define NTHR    512
#define COUT    10

#define NG      8           // 4-k groups per thread (32 k's)
#define RG      3           // register-resident weight groups
#define SG      (NG - RG)   // 5 groups from smem

#define XSTRIDE 1032        // x row stride (floats), bank-skewed
#define HSTR    152         // h row stride (floats), bank-skewed
#define HBUF    (MBLK * HSTR)   // 608 floats per h buffer

// h skew: float index for h[k] within a row = k + (k>>5)*8
// -> the 4 kq 32-blocks start at bank offsets {0,8,16,24}: conflict-free.
__device__ __forceinline__ int hoff(int k) { return k + ((k >> 5) << 3); }

// ---- dynamic smem layout (bytes, 16B aligned) ----
#define WS_OFF    0
#define WS_BYTES  (SG * 4 * NTHR * 16)      // 163840: ulonglong2 [(sg*4+q)][tid]
#define XS_OFF    (WS_OFF + WS_BYTES)
#define XS_BYTES  (MBLK * XSTRIDE * 4)      // 16512
#define WPS_OFF   (XS_OFF + XS_BYTES + 48)  // keep 16B alignment
#define WPS_BYTES (H * COUT * 4)            // 5120
#define HB_OFF    (WPS_OFF + WPS_BYTES)
#define HB_BYTES  (2 * HBUF * 4)            // 4864
#define SMEM_TOTAL (HB_OFF + HB_BYTES + 64) // ~190 KB <= 227 KB

__device__ __forceinline__ u64 pk2(float lo, float hi) {
    u64 r;
    asm("mov.b64 %0, {%1, %2};" : "=l"(r) : "f"(lo), "f"(hi));
    return r;
}
__device__ __forceinline__ void upk2(u64 v, float& lo, float& hi) {
    asm("mov.b64 {%0, %1}, %2;" : "=f"(lo), "=f"(hi) : "l"(v));
}
__device__ __forceinline__ u64 ffma2(u64 a, u64 b, u64 c) {
    u64 d;
    asm("fma.rn.f32x2 %0, %1, %2, %3;" : "=l"(d) : "l"(a), "l"(b), "l"(c));
    return d;
}

// Overflow-safe fast tanh / sigmoid (validated rel_err ~3e-7 across R1-R5).
__device__ __forceinline__ float tanh_fast(float x) {
    float a = fabsf(x);
    float e = __expf(2.0f * a);
    float r = 1.0f - __fdividef(2.0f, e + 1.0f);
    return copysignf(r, x);
}
__device__ __forceinline__ float sigmoid_fast(float x) {
    float e = __expf(-x);
    return __fdividef(1.0f, 1.0f + e);
}

__global__ void __launch_bounds__(NTHR, 1)
lstm_persistent_kernel(const float* __restrict__ x,
                       const float* __restrict__ Wgx, const float* __restrict__ Wgh, const float* __restrict__ bg,
                       const float* __restrict__ Wix, const float* __restrict__ Wih, const float* __restrict__ bi,
                       const float* __restrict__ Wfx, const float* __restrict__ Wfh, const float* __restrict__ bf,
                       const float* __restrict__ Wox, const float* __restrict__ Woh, const float* __restrict__ bo,
                       const float* __restrict__ Wph, const float* __restrict__ bp,
                       float* __restrict__ out)
{
    extern __shared__ char smem[];
    ulonglong2* ws = (ulonglong2*)(smem + WS_OFF);
    float*     xsm = (float*)(smem + XS_OFF);
    float*     wps = (float*)(smem + WPS_OFF);
    float*      hb = (float*)(smem + HB_OFF);   // two skewed h buffers

    const int tid = threadIdx.x;
    const int kq  = tid & 3;        // k slice: [kq*32, kq*32+32); also owned row m
    const int n   = tid >> 2;       // gate column (owns cols n of all 4 gates)
    const int m0  = blockIdx.x * MBLK;

    // ---- smem weights: this thread's groups RG..NG-1 ----
    // ws[(sg*4+q)*NTHR + tid]: q0={g,i}p0 q1={f,o}p0 q2={g,i}p1 q3={f,o}p1
    // (p0 = k-pair (k0,k1), p1 = (k2,k3))
#pragma unroll
    for (int sg = 0; sg < SG; sg++) {
        int k0 = kq * 32 + (RG + sg) * 4;
        ulonglong2 v;
        v.x = pk2(Wgh[(k0+0)*H+n], Wgh[(k0+1)*H+n]);
        v.y = pk2(Wih[(k0+0)*H+n], Wih[(k0+1)*H+n]);
        ws[(sg*4+0)*NTHR + tid] = v;
        v.x = pk2(Wfh[(k0+0)*H+n], Wfh[(k0+1)*H+n]);
        v.y = pk2(Woh[(k0+0)*H+n], Woh[(k0+1)*H+n]);
        ws[(sg*4+1)*NTHR + tid] = v;
        v.x = pk2(Wgh[(k0+2)*H+n], Wgh[(k0+3)*H+n]);
        v.y = pk2(Wih[(k0+2)*H+n], Wih[(k0+3)*H+n]);
        ws[(sg*4+2)*NTHR + tid] = v;
        v.x = pk2(Wfh[(k0+2)*H+n], Wfh[(k0+3)*H+n]);
        v.y = pk2(Woh[(k0+2)*H+n], Woh[(k0+3)*H+n]);
        ws[(sg*4+3)*NTHR + tid] = v;
    }

    // ---- register weights: groups 0..RG-1 (8 u64 each = 48 regs total) ----
    u64 wreg[RG][8];
#pragma unroll
    for (int g = 0; g < RG; g++) {
        int k0 = kq * 32 + g * 4;
        wreg[g][0] = pk2(Wgh[(k0+0)*H+n], Wgh[(k0+1)*H+n]);
        wreg[g][1] = pk2(Wih[(k0+0)*H+n], Wih[(k0+1)*H+n]);
        wreg[g][2] = pk2(Wfh[(k0+0)*H+n], Wfh[(k0+1)*H+n]);
        wreg[g][3] = pk2(Woh[(k0+0)*H+n], Woh[(k0+1)*H+n]);
        wreg[g][4] = pk2(Wgh[(k0+2)*H+n], Wgh[(k0+3)*H+n]);
        wreg[g][5] = pk2(Wih[(k0+2)*H+n], Wih[(k0+3)*H+n]);
        wreg[g][6] = pk2(Wfh[(k0+2)*H+n], Wfh[(k0+3)*H+n]);
        wreg[g][7] = pk2(Woh[(k0+2)*H+n], Woh[(k0+3)*H+n]);
    }

    // ---- gate-phase params: thread owns cell (row = kq, col n) ----
    const float wxg = Wgx[n], wxi = Wix[n], wxf = Wfx[n], wxo = Wox[n];
    const float bG = bg[(m0+kq)*H+n], bI = bi[(m0+kq)*H+n];
    const float bF = bf[(m0+kq)*H+n], bO = bo[(m0+kq)*H+n];

    // ---- preload x, Wph, zero both h buffers ----
    for (int i = tid; i < MBLK * SEQ; i += NTHR) {
        int mm = i >> 10, tt = i & (SEQ - 1);
        xsm[mm * XSTRIDE + tt] = x[(m0+mm)*SEQ + tt];
    }
    for (int i = tid; i < H * COUT; i += NTHR) wps[i] = Wph[i];
    for (int i = tid; i < 2 * HBUF; i += NTHR) hb[i] = 0.0f;
    float c = 0.0f;
    __syncthreads();

    // per-thread constant offsets
    const int hload0 = kq * 40;              // kq*32 + kq*8 (skew), +g*4 per group
    const int hstore = kq * HSTR + hoff(n);  // own cell in the write buffer
    const float* xrow = xsm + kq * XSTRIDE;
    const bool b0 = (kq & 1) != 0;
    const bool b1 = (kq & 2) != 0;

    // ---- time loop: ONE barrier per step ----
    for (int t = 0; t < SEQ; t++) {
        const float* hr = hb + ((t & 1) ? HBUF : 0);
        float*       hw = hb + ((t & 1) ? 0 : HBUF);

        u64 acc[4][4];   // [gate][m], k-pair packed
#pragma unroll
        for (int gg = 0; gg < 4; gg++)
#pragma unroll
            for (int m = 0; m < 4; m++) acc[gg][m] = 0ull;

#pragma unroll
        for (int g = 0; g < NG; g++) {
            u64 wg0, wi0, wf0, wo0, wg1, wi1, wf1, wo1;
            if (g < RG) {
                wg0 = wreg[g][0]; wi0 = wreg[g][1]; wf0 = wreg[g][2]; wo0 = wreg[g][3];
                wg1 = wreg[g][4]; wi1 = wreg[g][5]; wf1 = wreg[g][6]; wo1 = wreg[g][7];
            } else {
                int sg = g - RG;
                ulonglong2 q0 = ws[(sg*4+0)*NTHR + tid];
                ulonglong2 q1 = ws[(sg*4+1)*NTHR + tid];
                ulonglong2 q2 = ws[(sg*4+2)*NTHR + tid];
                ulonglong2 q3 = ws[(sg*4+3)*NTHR + tid];
                wg0 = q0.x; wi0 = q0.y; wf0 = q1.x; wo0 = q1.y;
                wg1 = q2.x; wi1 = q2.y; wf1 = q3.x; wo1 = q3.y;
            }
            const int hbase = hload0 + (g << 2);
#pragma unroll
            for (int m = 0; m < 4; m++) {
                // 16B load: {h[k0..k3]} of row m; 4 kq spans at banks {0,8,16,24}
                ulonglong2 hu = *(const ulonglong2*)(hr + m * HSTR + hbase);
                acc[0][m] = ffma2(hu.x, wg0, acc[0][m]);
                acc[1][m] = ffma2(hu.x, wi0, acc[1][m]);
                acc[2][m] = ffma2(hu.x, wf0, acc[2][m]);
                acc[3][m] = ffma2(hu.x, wo0, acc[3][m]);
                acc[0][m] = ffma2(hu.y, wg1, acc[0][m]);
                acc[1][m] = ffma2(hu.y, wi1, acc[1][m]);
                acc[2][m] = ffma2(hu.y, wf1, acc[2][m]);
                acc[3][m] = ffma2(hu.y, wo1, acc[3][m]);
            }
        }

        // collapse f32x2 pairs -> p[gate][m]
        float p[4][4];
#pragma unroll
        for (int gg = 0; gg < 4; gg++)
#pragma unroll
            for (int m = 0; m < 4; m++) {
                float lo, hi;
                upk2(acc[gg][m], lo, hi);
                p[gg][m] = lo + hi;
            }

        // butterfly reduce across the 4 kq lanes -> z[gate] for row m = kq
        float z[4];
#pragma unroll
        for (int gg = 0; gg < 4; gg++) {
            float t0 = __shfl_xor_sync(0xFFFFFFFFu, b0 ? p[gg][0] : p[gg][1], 1);
            float qlo = (b0 ? p[gg][1] : p[gg][0]) + t0;
            float t1 = __shfl_xor_sync(0xFFFFFFFFu, b0 ? p[gg][2] : p[gg][3], 1);
            float qhi = (b0 ? p[gg][3] : p[gg][2]) + t1;
            float t2 = __shfl_xor_sync(0xFFFFFFFFu, b1 ? qlo : qhi, 2);
            z[gg] = (b1 ? qhi : qlo) + t2;
        }

        // gates + state update for cell (row kq, col n)
        {
            float xv = xrow[t];
            float zg = z[0] + fmaf(xv, wxg, bG);
            float zi = z[1] + fmaf(xv, wxi, bI);
            float zf = z[2] + fmaf(xv, wxf, bF);
            float zo = z[3] + fmaf(xv, wxo, bO);
            float gg = tanh_fast(zg);
            float ii = sigmoid_fast(zi);
            float ff = sigmoid_fast(zf);
            float oo = sigmoid_fast(zo);
            c = fmaf(gg, ii, c * ff);
            hw[hstore] = tanh_fast(c) * oo;
        }
        __syncthreads();   // all reads of hr precede own store; one barrier suffices
    }

    // ---- final projection: h ends in buffer 0 after SEQ (even) steps ----
    const float* hf = hb;
    if (tid < MBLK * COUT) {
        int m = tid / COUT, cc = tid - m * COUT;
        float ssum = bp[(m0+m)*COUT + cc];
#pragma unroll 16
        for (int k = 0; k < H; k++)
            ssum = fmaf(hf[m * HSTR + hoff(k)], wps[k*COUT + cc], ssum);
        out[(m0+m)*COUT + cc] = ssum;
    }
}

extern "C" void kernel_launch(void* const* d_in, const int* in_sizes, int n_in,
                              void* d_out, int out_size) {
    const float* x   = (const float*)d_in[0];
    const float* Wgx = (const float*)d_in[1];
    const float* Wgh = (const float*)d_in[2];
    const float* bg  = (const float*)d_in[3];
    const float* Wix = (const float*)d_in[4];
    const float* Wih = (const float*)d_in[5];
    const float* bi  = (const float*)d_in[6];
    const float* Wfx = (const float*)d_in[7];
    const float* Wfh = (const float*)d_in[8];
    const float* bf  = (const float*)d_in[9];
    const float* Wox = (const float*)d_in[10];
    const float* Woh = (const float*)d_in[11];
    const float* bo  = (const float*)d_in[12];
    const float* Wph = (const float*)d_in[13];
    const float* bp  = (const float*)d_in[14];
    float* out = (float*)d_out;

    cudaFuncSetAttribute(lstm_persistent_kernel,
                         cudaFuncAttributeMaxDynamicSharedMemorySize, SMEM_TOTAL);

    lstm_persistent_kernel<<<NCTAS, NTHR, SMEM_TOTAL>>>(
        x, Wgx, Wgh, bg, Wix, Wih, bi, Wfx, Wfh, bf, Wox, Woh, bo, Wph, bp, out);
}

// round 8
// speedup vs baseline: 2.0975x; 1.1124x over previous
#include <cuda_runtime.h>

typedef unsigned long long u64;

#define H       128
#define SEQ     1024
#define MBLK    4
#define NCTAS   128
#define NTHR    256
#define COUT    10

#define NG      16          // 4-k groups per thread (64 k's, kh half)
#define RG      7           // register-resident weight groups
#define PFG     2           // groups prefetched during the tail
#define SG      (NG - RG)   // 9 groups live in smem (2 prefetched, 7 in-loop)

#define HSTRIDE 136         // h row stride in floats (mod 32 = 8 -> bank spread)
#define HBUF    (MBLK * HSTRIDE)    // 544 floats

// h skew: float offset of h[k] within a row = k + (k>>6)*4
// kh=1 half starts at 68 -> +4 banks vs kh=0: the two 16B spans of a
// broadcast load are bank-disjoint -> 1 wavefront.
__device__ __forceinline__ int hoff(int k) { return k + ((k >> 6) << 2); }

// ---- dynamic smem layout (bytes, 16B aligned) ----
#define WS_OFF    0
#define WS_BYTES  (SG * 4 * NTHR * 16)      // 147456
#define XS_OFF    (WS_OFF + WS_BYTES)
#define XS_BYTES  (MBLK * SEQ * 4)          // 16384
#define WPS_OFF   (XS_OFF + XS_BYTES)
#define WPS_BYTES (H * COUT * 4)            // 5120
#define HB_OFF    (WPS_OFF + WPS_BYTES)
#define HB_BYTES  (2 * HBUF * 4)            // 4352
#define SMEM_TOTAL (HB_OFF + HB_BYTES + 64) // ~173 KB <= 227 KB

__device__ __forceinline__ u64 pk2(float lo, float hi) {
    u64 r;
    asm("mov.b64 %0, {%1, %2};" : "=l"(r) : "f"(lo), "f"(hi));
    return r;
}
__device__ __forceinline__ void upk2(u64 v, float& lo, float& hi) {
    asm("mov.b64 {%0, %1}, %2;" : "=f"(lo), "=f"(hi) : "l"(v));
}
__device__ __forceinline__ u64 ffma2(u64 a, u64 b, u64 c) {
    u64 d;
    asm("fma.rn.f32x2 %0, %1, %2, %3;" : "=l"(d) : "l"(a), "l"(b), "l"(c));
    return d;
}

// Fused LSTM cell epilogue: h = tanh(c')*sigmoid(zo), c' = tanh(zg)*sigmoid(zi) + c*sigmoid(zf)
// Combined rcp's: 5 exp + 3 rcp = 8 MUFU (vs 10). Overflow-safe:
// exp->inf makes the denominator inf -> quotient 0 (correct saturation); no 0*inf paths.
__device__ __forceinline__ float lstm_cell(float zg, float zi, float zf, float zo, float& c) {
    float eg = __expf(-2.0f * fabsf(zg));
    float ei = __expf(-zi);
    float ef = __expf(-zf);
    float eo = __expf(-zo);
    float gi = __fdividef(copysignf(1.0f - eg, zg), (1.0f + eg) * (1.0f + ei));
    float cf = __fdividef(c, 1.0f + ef);
    float cn = gi + cf;
    float ec = __expf(-2.0f * fabsf(cn));
    float h  = __fdividef(copysignf(1.0f - ec, cn), (1.0f + ec) * (1.0f + eo));
    c = cn;
    return h;
}

__global__ void __launch_bounds__(NTHR, 1)
lstm_persistent_kernel(const float* __restrict__ x,
                       const float* __restrict__ Wgx, const float* __restrict__ Wgh, const float* __restrict__ bg,
                       const float* __restrict__ Wix, const float* __restrict__ Wih, const float* __restrict__ bi,
                       const float* __restrict__ Wfx, const float* __restrict__ Wfh, const float* __restrict__ bf,
                       const float* __restrict__ Wox, const float* __restrict__ Woh, const float* __restrict__ bo,
                       const float* __restrict__ Wph, const float* __restrict__ bp,
                       float* __restrict__ out)
{
    extern __shared__ char smem[];
    ulonglong2* ws = (ulonglong2*)(smem + WS_OFF);
    float*     xsm = (float*)(smem + XS_OFF);
    float*     wps = (float*)(smem + WPS_OFF);
    float*      hb = (float*)(smem + HB_OFF);   // two skewed h buffers

    const int tid = threadIdx.x;
    const int kh  = tid & 1;        // k-half: [kh*64, kh*64+64); partner = adjacent lane
    const int n   = tid >> 1;       // gate column (owns cols n of all 4 gates)
    const int m0  = blockIdx.x * MBLK;
    const int mr  = kh * 2;         // this thread's gate-phase rows: mr, mr+1
    const int om  = 2 - mr;         // partner's rows

    // ---- smem weights: groups RG..NG-1 of slice (kh, n) ----
    // ws[(sg*4+q)*NTHR + tid]: q0={g,i}(k0,k1) q1={f,o}(k0,k1) q2={g,i}(k2,k3) q3={f,o}(k2,k3)
#pragma unroll
    for (int sg = 0; sg < SG; sg++) {
        int k0 = kh * 64 + (RG + sg) * 4;
        ulonglong2 v;
        v.x = pk2(Wgh[(k0+0)*H+n], Wgh[(k0+1)*H+n]);
        v.y = pk2(Wih[(k0+0)*H+n], Wih[(k0+1)*H+n]);
        ws[(sg*4+0)*NTHR + tid] = v;
        v.x = pk2(Wfh[(k0+0)*H+n], Wfh[(k0+1)*H+n]);
        v.y = pk2(Woh[(k0+0)*H+n], Woh[(k0+1)*H+n]);
        ws[(sg*4+1)*NTHR + tid] = v;
        v.x = pk2(Wgh[(k0+2)*H+n], Wgh[(k0+3)*H+n]);
        v.y = pk2(Wih[(k0+2)*H+n], Wih[(k0+3)*H+n]);
        ws[(sg*4+2)*NTHR + tid] = v;
        v.x = pk2(Wfh[(k0+2)*H+n], Wfh[(k0+3)*H+n]);
        v.y = pk2(Woh[(k0+2)*H+n], Woh[(k0+3)*H+n]);
        ws[(sg*4+3)*NTHR + tid] = v;
    }

    // ---- register weights: groups 0..RG-1 (8 u64 each = 112 regs) ----
    u64 wreg[RG][8];
#pragma unroll
    for (int g = 0; g < RG; g++) {
        int k0 = kh * 64 + g * 4;
        wreg[g][0] = pk2(Wgh[(k0+0)*H+n], Wgh[(k0+1)*H+n]);
        wreg[g][1] = pk2(Wih[(k0+0)*H+n], Wih[(k0+1)*H+n]);
        wreg[g][2] = pk2(Wfh[(k0+0)*H+n], Wfh[(k0+1)*H+n]);
        wreg[g][3] = pk2(Woh[(k0+0)*H+n], Woh[(k0+1)*H+n]);
        wreg[g][4] = pk2(Wgh[(k0+2)*H+n], Wgh[(k0+3)*H+n]);
        wreg[g][5] = pk2(Wih[(k0+2)*H+n], Wih[(k0+3)*H+n]);
        wreg[g][6] = pk2(Wfh[(k0+2)*H+n], Wfh[(k0+3)*H+n]);
        wreg[g][7] = pk2(Woh[(k0+2)*H+n], Woh[(k0+3)*H+n]);
    }

    // ---- gate-phase params: thread owns cells (mr, n), (mr+1, n) ----
    const float wxg = Wgx[n], wxi = Wix[n], wxf = Wfx[n], wxo = Wox[n];
    float bG[2], bI[2], bF[2], bO[2];
#pragma unroll
    for (int j = 0; j < 2; j++) {
        bG[j] = bg[(m0+mr+j)*H+n];
        bI[j] = bi[(m0+mr+j)*H+n];
        bF[j] = bf[(m0+mr+j)*H+n];
        bO[j] = bo[(m0+mr+j)*H+n];
    }

    // ---- preload x, Wph, zero both h buffers ----
    for (int i = tid; i < MBLK * SEQ; i += NTHR) {
        int mm = i >> 10, tt = i & (SEQ - 1);
        xsm[i] = x[(m0+mm)*SEQ + tt];
    }
    for (int i = tid; i < H * COUT; i += NTHR) wps[i] = Wph[i];
    for (int i = tid; i < 2 * HBUF; i += NTHR) hb[i] = 0.0f;
    float c0 = 0.0f, c1 = 0.0f;
    __syncthreads();

    // per-thread constant offsets
    const int hload0 = kh * 68;                         // skewed base of this kh half
    const int hst0 = (mr + 0) * HSTRIDE + hoff(n);      // own h store offsets
    const int hst1 = (mr + 1) * HSTRIDE + hoff(n);
    const float* x0 = xsm + (mr + 0) * SEQ;
    const float* x1 = xsm + (mr + 1) * SEQ;

    // ---- initial prefetch of smem groups RG, RG+1 (consumed in FMA phase) ----
    ulonglong2 pf[PFG * 4];
#pragma unroll
    for (int i = 0; i < PFG * 4; i++) pf[i] = ws[i * NTHR + tid];

    // ---- time loop: ONE barrier per step ----
    for (int t = 0; t < SEQ; t++) {
        const float* hr = hb + ((t & 1) ? HBUF : 0);
        float*       hw = hb + ((t & 1) ? 0 : HBUF);

        u64 acc[4][4];   // [gate][m], k-pair packed (even/odd k in lo/hi)
#pragma unroll
        for (int gg = 0; gg < 4; gg++)
#pragma unroll
            for (int m = 0; m < 4; m++) acc[gg][m] = 0ull;

#pragma unroll
        for (int g = 0; g < NG; g++) {
            u64 wg0, wi0, wf0, wo0, wg1, wi1, wf1, wo1;
            if (g < RG) {
                wg0 = wreg[g][0]; wi0 = wreg[g][1]; wf0 = wreg[g][2]; wo0 = wreg[g][3];
                wg1 = wreg[g][4]; wi1 = wreg[g][5]; wf1 = wreg[g][6]; wo1 = wreg[g][7];
            } else if (g < RG + PFG) {
                int b = (g - RG) * 4;
                wg0 = pf[b+0].x; wi0 = pf[b+0].y; wf0 = pf[b+1].x; wo0 = pf[b+1].y;
                wg1 = pf[b+2].x; wi1 = pf[b+2].y; wf1 = pf[b+3].x; wo1 = pf[b+3].y;
            } else {
                int sg = g - RG;
                ulonglong2 q0 = ws[(sg*4+0)*NTHR + tid];
                ulonglong2 q1 = ws[(sg*4+1)*NTHR + tid];
                ulonglong2 q2 = ws[(sg*4+2)*NTHR + tid];
                ulonglong2 q3 = ws[(sg*4+3)*NTHR + tid];
                wg0 = q0.x; wi0 = q0.y; wf0 = q1.x; wo0 = q1.y;
                wg1 = q2.x; wi1 = q2.y; wf1 = q3.x; wo1 = q3.y;
            }
            const int hbase = hload0 + (g << 2);
#pragma unroll
            for (int m = 0; m < 4; m++) {
                // broadcast 16B: {h[k0..k3]} of row m; 2 kh spans bank-disjoint -> 1 wf
                ulonglong2 hu = *(const ulonglong2*)(hr + m * HSTRIDE + hbase);
                acc[0][m] = ffma2(hu.x, wg0, acc[0][m]);
                acc[1][m] = ffma2(hu.x, wi0, acc[1][m]);
                acc[2][m] = ffma2(hu.x, wf0, acc[2][m]);
                acc[3][m] = ffma2(hu.x, wo0, acc[3][m]);
                acc[0][m] = ffma2(hu.y, wg1, acc[0][m]);
                acc[1][m] = ffma2(hu.y, wi1, acc[1][m]);
                acc[2][m] = ffma2(hu.y, wf1, acc[2][m]);
                acc[3][m] = ffma2(hu.y, wo1, acc[3][m]);
            }
        }

        // collapse k-pairs -> p[gate][m] (this thread's kh-partial sums)
        float p[4][4];
#pragma unroll
        for (int gg = 0; gg < 4; gg++)
#pragma unroll
            for (int m = 0; m < 4; m++) {
                float lo, hi;
                upk2(acc[gg][m], lo, hi);
                p[gg][m] = lo + hi;
            }

        // exchange kh-partials with adjacent lane: send partner's rows, get mine
        float rec[4][2];
#pragma unroll
        for (int gg = 0; gg < 4; gg++)
#pragma unroll
            for (int j = 0; j < 2; j++)
                rec[gg][j] = __shfl_xor_sync(0xFFFFFFFFu, p[gg][om + j], 1);

        // gates for the 2 owned cells
        {
            float xv = x0[t];
            float zg = p[0][mr]   + rec[0][0] + fmaf(xv, wxg, bG[0]);
            float zi = p[1][mr]   + rec[1][0] + fmaf(xv, wxi, bI[0]);
            float zf = p[2][mr]   + rec[2][0] + fmaf(xv, wxf, bF[0]);
            float zo = p[3][mr]   + rec[3][0] + fmaf(xv, wxo, bO[0]);
            hw[hst0] = lstm_cell(zg, zi, zf, zo, c0);
        }
        {
            float xv = x1[t];
            float zg = p[0][mr+1] + rec[0][1] + fmaf(xv, wxg, bG[1]);
            float zi = p[1][mr+1] + rec[1][1] + fmaf(xv, wxi, bI[1]);
            float zf = p[2][mr+1] + rec[2][1] + fmaf(xv, wxf, bF[1]);
            float zo = p[3][mr+1] + rec[3][1] + fmaf(xv, wxo, bO[1]);
            hw[hst1] = lstm_cell(zg, zi, zf, zo, c1);
        }

        // prefetch next step's first 2 smem groups during the tail (step-invariant data)
#pragma unroll
        for (int i = 0; i < PFG * 4; i++) pf[i] = ws[i * NTHR + tid];

        __syncthreads();   // new h visible; double-buffer makes one barrier sufficient
    }

    // ---- final projection: h ends in buffer 0 after SEQ (even) steps ----
    const float* hf = hb;
    if (tid < MBLK * COUT) {
        int m = tid / COUT, cc = tid - m * COUT;
        float ssum = bp[(m0+m)*COUT + cc];
#pragma unroll 16
        for (int k = 0; k < H; k++)
            ssum = fmaf(hf[m * HSTRIDE + hoff(k)], wps[k*COUT + cc], ssum);
        out[(m0+m)*COUT + cc] = ssum;
    }
}

extern "C" void kernel_launch(void* const* d_in, const int* in_sizes, int n_in,
                              void* d_out, int out_size) {
    const float* x   = (const float*)d_in[0];
    const float* Wgx = (const float*)d_in[1];
    const float* Wgh = (const float*)d_in[2];
    const float* bg  = (const float*)d_in[3];
    const float* Wix = (const float*)d_in[4];
    const float* Wih = (const float*)d_in[5];
    const float* bi  = (const float*)d_in[6];
    const float* Wfx = (const float*)d_in[7];
    const float* Wfh = (const float*)d_in[8];
    const float* bf  = (const float*)d_in[9];
    const float* Wox = (const float*)d_in[10];
    const float* Woh = (const float*)d_in[11];
    const float* bo  = (const float*)d_in[12];
    const float* Wph = (const float*)d_in[13];
    const float* bp  = (const float*)d_in[14];
    float* out = (float*)d_out;

    cudaFuncSetAttribute(lstm_persistent_kernel,
                         cudaFuncAttributeMaxDynamicSharedMemorySize, SMEM_TOTAL);

    lstm_persistent_kernel<<<NCTAS, NTHR, SMEM_TOTAL>>>(
        x, Wgx, Wgh, bg, Wix, Wih, bi, Wfx, Wfh, bf, Wox, Woh, bo, Wph, bp, out);
}